// round 12
// baseline (speedup 1.0000x reference)
#include <cuda_runtime.h>
#include <cuda_bf16.h>
#include <math.h>
#include <stdint.h>

#define Bb    2
#define CIN   256
#define FF    512
#define COUT  256
#define NH    8
#define DH    64
#define NTOK  2048
#define TB    128
#define Tt    16
#define KSCALE (0.08654104f)   // log2(e)/16
#define BN_EPS 1e-5f

// ---------------- scratch (bf16 packed in uint32 words) ----------------
__device__ uint32_t g_Wb[4*65536];        // WK,WQ,WV rows 128w; Wo rows 256w
__device__ uint32_t g_Xt[Bb*NTOK*(CIN/2)];// [b][n][c/2]
__device__ uint32_t g_Kb[Bb*NTOK*FF/2];   // [b][n][f/2]  (pre-scaled log2e/16)
__device__ uint32_t g_Qb[Bb*NTOK*FF/2];   // [b][n][f/2]
__device__ uint32_t g_Vb[Bb*FF*NTOK/2];   // [b][f][n/2]
__device__ uint32_t g_Vo[Bb*NTOK*FF/2];   // [b][n][f/2]
__device__ float g_y [Bb*COUT*NTOK];      // [b][c][n]
__device__ uint32_t g_Opb[Bb*NH*12*4*TB*(DH/2)];  // partials (it>=4), bf16
__device__ float g_lp[Bb*NH*12*4*TB];
__device__ float g_ps[COUT*64];
__device__ float g_pq[COUT*64];
__device__ float g_mean[COUT];
__device__ float g_istd[COUT];

// 40 units per bh, chunk = 4 j-tiles (128 tokens each), LPT order
__constant__ int8_t U_IT[40] = {3,4,5,6,7,7,8,8,9,9,10,10,11,11,11,12,12,12,
                                13,13,13,14,14,14,15,15,15,15,
                                2,6,10,14, 1,5,9,13, 0,4,8,12};
__constant__ int8_t U_CH[40] = {0,0,0,0,0,1,0,1,0,1,0,1,0,1,2,0,1,2,
                                0,1,2,0,1,2,0,1,2,3,
                                0,1,2,3, 0,1,2,3, 0,1,2,3};

// ---------------- helpers ----------------
__device__ __forceinline__ uint32_t pack_bf16(float lo, float hi) {
    uint32_t r;
    asm("cvt.rn.bf16x2.f32 %0, %1, %2;" : "=r"(r) : "f"(hi), "f"(lo));
    return r;
}
__device__ __forceinline__ float ex2f(float x) {
    float y;
    asm("ex2.approx.f32 %0, %1;" : "=f"(y) : "f"(x));
    return y;
}
__device__ __forceinline__ void mma4(float d[4], const uint32_t a[4],
                                     uint32_t b0, uint32_t b1)
{
    asm volatile(
      "mma.sync.aligned.m16n8k16.row.col.f32.bf16.bf16.f32 "
      "{%0,%1,%2,%3}, {%4,%5,%6,%7}, {%8,%9}, {%0,%1,%2,%3};"
      : "+f"(d[0]), "+f"(d[1]), "+f"(d[2]), "+f"(d[3])
      : "r"(a[0]), "r"(a[1]), "r"(a[2]), "r"(a[3]), "r"(b0), "r"(b1));
}
__device__ __forceinline__ void ldsm4(uint32_t r[4], uint32_t addr) {
    asm volatile("ldmatrix.sync.aligned.m8n8.x4.shared.b16 {%0,%1,%2,%3}, [%4];"
        : "=r"(r[0]), "=r"(r[1]), "=r"(r[2]), "=r"(r[3]) : "r"(addr));
}
__device__ __forceinline__ uint32_t smem_u32(const void* p) {
    return (uint32_t)__cvta_generic_to_shared(p);
}
__device__ __forceinline__ void cp16(uint32_t s, const void* g) {
    asm volatile("cp.async.cg.shared.global [%0], [%1], 16;" :: "r"(s), "l"(g));
}
#define CP_COMMIT asm volatile("cp.async.commit_group;")
#define CP_WAIT0  asm volatile("cp.async.wait_group 0;")

__device__ __forceinline__ uint32_t laneA(int l, int S) {
    return (uint32_t)((((l&7) + ((l>>3)&1)*8)*S + (l>>4)*4) * 4);
}
__device__ __forceinline__ uint32_t laneB(int l, int S) {
    return (uint32_t)((((l&7) + ((l>>4)&1)*8)*S + ((l>>3)&1)*4) * 4);
}

// ---------------- prep: weights -> bf16; X -> bf16 transposed ------------
__global__ __launch_bounds__(256) void prep_kernel(
    const float* __restrict__ WK, const float* __restrict__ WQ,
    const float* __restrict__ WV, const float* __restrict__ Wo,
    const float* __restrict__ X)
{
    const int tid = threadIdx.x;
    if (blockIdx.x < 256) {
        int e8 = blockIdx.x*256 + tid;
        int e  = e8*8;
        const float* src; int off;
        if      (e < 131072) { src = WK; off = e; }
        else if (e < 262144) { src = WQ; off = e - 131072; }
        else if (e < 393216) { src = WV; off = e - 262144; }
        else                 { src = Wo; off = e - 393216; }
        float4 a = *(const float4*)(src + off);
        float4 c = *(const float4*)(src + off + 4);
        uint4 o;
        o.x = pack_bf16(a.x, a.y); o.y = pack_bf16(a.z, a.w);
        o.z = pack_bf16(c.x, c.y); o.w = pack_bf16(c.z, c.w);
        *(uint4*)(g_Wb + e8*4) = o;
    } else {
        __shared__ float ts[32][68];
        int bx = blockIdx.x - 256;
        int b  = bx >> 8;
        int t8 = bx & 255;
        int n0 = (t8 >> 3) * 64;
        int c0 = (t8 & 7) * 32;
        const float* Xb = X + (size_t)b*CIN*NTOK;
        #pragma unroll
        for (int i = 0; i < 2; i++) {
            int c = (tid>>4) + i*16, n4 = (tid&15)*4;
            float4 v = *(const float4*)(Xb + (size_t)(c0+c)*NTOK + n0 + n4);
            *(float4*)&ts[c][n4] = v;
        }
        __syncthreads();
        int n = tid>>2, w0 = tid&3;
        size_t dst = ((size_t)b*NTOK + n0 + n)*128 + (c0>>1);
        #pragma unroll
        for (int ii = 0; ii < 4; ii++) {
            int w = w0 + 4*ii;
            g_Xt[dst + w] = pack_bf16(ts[2*w][n], ts[2*w+1][n]);
        }
    }
}

// ---------------- fused QKV GEMM: grid (32,12,2) -------------------------
__global__ __launch_bounds__(256) void qkv_kernel(
    uint32_t* __restrict__ Kb, uint32_t* __restrict__ Qb,
    uint32_t* __restrict__ Vb)
{
    __shared__ __align__(16) uint32_t Wsu[2][128*20];
    __shared__ __align__(16) uint32_t Xsu[2][64*20];
    const int b = blockIdx.z, mb = blockIdx.y, n0 = blockIdx.x*64;
    const int sel = mb >> 2, m0 = (mb & 3)*128;
    const uint32_t* W  = g_Wb + sel*65536;
    const uint32_t* Xp = g_Xt + ((size_t)b*NTOK + n0)*128;
    const int tid = threadIdx.x, w = tid>>5, lane = tid&31;
    const int g = lane>>2, j = lane&3, wrow = w*16;
    const uint32_t oA = laneA(lane, 20), oB = laneB(lane, 20);

    float sf[8][4];
    #pragma unroll
    for (int nt=0;nt<8;nt++){ sf[nt][0]=sf[nt][1]=sf[nt][2]=sf[nt][3]=0.f; }

    #pragma unroll
    for (int i=0;i<2;i++){
        int idx = tid + i*256, m = idx>>2, seg = idx&3;
        cp16(smem_u32(&Wsu[0][m*20 + seg*4]), W + (size_t)(m0+m)*128 + seg*4);
    }
    {   int r = tid>>2, seg = tid&3;
        cp16(smem_u32(&Xsu[0][r*20 + seg*4]), Xp + (size_t)r*128 + seg*4);
    }
    CP_COMMIT;

    for (int c = 0; c < 8; c++) {
        int cur = c & 1;
        CP_WAIT0;
        __syncthreads();
        if (c < 7) {
            #pragma unroll
            for (int i=0;i<2;i++){
                int idx = tid + i*256, m = idx>>2, seg = idx&3;
                cp16(smem_u32(&Wsu[cur^1][m*20 + seg*4]),
                     W + (size_t)(m0+m)*128 + (c+1)*16 + seg*4);
            }
            {   int r = tid>>2, seg = tid&3;
                cp16(smem_u32(&Xsu[cur^1][r*20 + seg*4]),
                     Xp + (size_t)r*128 + (c+1)*16 + seg*4);
            }
            CP_COMMIT;
        }
        const uint32_t wbase = smem_u32(Wsu[cur]) + wrow*20*4 + oA;
        const uint32_t xbase = smem_u32(Xsu[cur]) + oB;
        uint32_t a0[4], a1[4], bb[4];
        ldsm4(a0, wbase);
        ldsm4(a1, wbase + 8*4);
        #pragma unroll
        for (int ntp = 0; ntp < 4; ntp++) {
            ldsm4(bb, xbase + (ntp*16*20)*4);
            mma4(sf[2*ntp],   a0, bb[0], bb[1]);
            mma4(sf[2*ntp+1], a0, bb[2], bb[3]);
            ldsm4(bb, xbase + (ntp*16*20 + 8)*4);
            mma4(sf[2*ntp],   a1, bb[0], bb[1]);
            mma4(sf[2*ntp+1], a1, bb[2], bb[3]);
        }
    }
    __syncthreads();

    if (sel == 2) {
        size_t basew = ((size_t)b*FF + m0)*1024 + (n0>>1);
        #pragma unroll
        for (int nt=0; nt<8; nt++) {
            Vb[basew + (size_t)(wrow+g  )*1024 + nt*4 + j] = pack_bf16(sf[nt][0], sf[nt][1]);
            Vb[basew + (size_t)(wrow+g+8)*1024 + nt*4 + j] = pack_bf16(sf[nt][2], sf[nt][3]);
        }
    } else {
        const float scale = (sel==0) ? KSCALE : 1.f;
        __nv_bfloat16* tileh = (__nv_bfloat16*)&Wsu[0][0];
        #pragma unroll
        for (int nt=0; nt<8; nt++) {
            int c = nt*8 + 2*j;
            tileh[(c  )*136 + wrow+g  ] = __float2bfloat16(sf[nt][0]*scale);
            tileh[(c+1)*136 + wrow+g  ] = __float2bfloat16(sf[nt][1]*scale);
            tileh[(c  )*136 + wrow+g+8] = __float2bfloat16(sf[nt][2]*scale);
            tileh[(c+1)*136 + wrow+g+8] = __float2bfloat16(sf[nt][3]*scale);
        }
        __syncthreads();
        uint32_t* C = (sel==0) ? Kb : Qb;
        const uint32_t* tw = (const uint32_t*)tileh;
        int cc = tid>>2, seg = tid&3;
        size_t dstw = ((size_t)b*NTOK + n0 + cc)*256 + (m0>>1) + seg*16;
        #pragma unroll
        for (int q=0; q<4; q++) {
            uint4 v = *(const uint4*)(tw + cc*68 + seg*16 + q*4);
            *(uint4*)(C + dstw + q*4) = v;
        }
    }
}

// ---------------- proj: grid (32,2,2) ------------------------------------
__global__ __launch_bounds__(256) void proj_kernel(
    const uint32_t* __restrict__ Vo,
    const float* __restrict__ bias, const float* __restrict__ skip,
    float* __restrict__ Y)
{
    __shared__ __align__(16) uint32_t Wsu[2][128*20];
    __shared__ __align__(16) uint32_t Xsu[2][64*20];
    const int b = blockIdx.z, m0 = blockIdx.y*128, n0 = blockIdx.x*64;
    const int tid = threadIdx.x, w = tid>>5, lane = tid&31;
    const int g = lane>>2, j = lane&3, wrow = w*16;
    const uint32_t* W  = g_Wb + 3*65536;
    const uint32_t* Vp = Vo + ((size_t)b*NTOK + n0)*256;
    const uint32_t oA = laneA(lane, 20), oB = laneB(lane, 20);

    float sf[8][4];
    #pragma unroll
    for (int nt=0;nt<8;nt++){ sf[nt][0]=sf[nt][1]=sf[nt][2]=sf[nt][3]=0.f; }

    #pragma unroll
    for (int i=0;i<2;i++){
        int idx = tid + i*256, m = idx>>2, seg = idx&3;
        cp16(smem_u32(&Wsu[0][m*20 + seg*4]), W + (size_t)(m0+m)*256 + seg*4);
    }
    {   int r = tid>>2, seg = tid&3;
        cp16(smem_u32(&Xsu[0][r*20 + seg*4]), Vp + (size_t)r*256 + seg*4);
    }
    CP_COMMIT;

    for (int c = 0; c < 16; c++) {
        int cur = c & 1;
        CP_WAIT0;
        __syncthreads();
        if (c < 15) {
            #pragma unroll
            for (int i=0;i<2;i++){
                int idx = tid + i*256, m = idx>>2, seg = idx&3;
                cp16(smem_u32(&Wsu[cur^1][m*20 + seg*4]),
                     W + (size_t)(m0+m)*256 + (c+1)*16 + seg*4);
            }
            {   int r = tid>>2, seg = tid&3;
                cp16(smem_u32(&Xsu[cur^1][r*20 + seg*4]),
                     Vp + (size_t)r*256 + (c+1)*16 + seg*4);
            }
            CP_COMMIT;
        }
        const uint32_t wbase = smem_u32(Wsu[cur]) + wrow*20*4 + oA;
        const uint32_t xbase = smem_u32(Xsu[cur]) + oB;
        uint32_t a0[4], a1[4], bb[4];
        ldsm4(a0, wbase);
        ldsm4(a1, wbase + 8*4);
        #pragma unroll
        for (int ntp = 0; ntp < 4; ntp++) {
            ldsm4(bb, xbase + (ntp*16*20)*4);
            mma4(sf[2*ntp],   a0, bb[0], bb[1]);
            mma4(sf[2*ntp+1], a0, bb[2], bb[3]);
            ldsm4(bb, xbase + (ntp*16*20 + 8)*4);
            mma4(sf[2*ntp],   a1, bb[0], bb[1]);
            mma4(sf[2*ntp+1], a1, bb[2], bb[3]);
        }
    }

    const int row0 = m0 + wrow + g, row1 = row0 + 8;
    const float b0v = bias[row0], b1v = bias[row1];
    const size_t ybase = (size_t)b*COUT*NTOK;
    float s0=0.f,q0=0.f,s1=0.f,q1=0.f;
    #pragma unroll
    for (int nt=0; nt<8; nt++) {
        int col = n0 + nt*8 + 2*j;
        float2 sk0 = *(const float2*)(skip + ybase + (size_t)row0*NTOK + col);
        float2 sk1 = *(const float2*)(skip + ybase + (size_t)row1*NTOK + col);
        float2 y0 = { fmaxf(sf[nt][0]+b0v,0.f)+sk0.x, fmaxf(sf[nt][1]+b0v,0.f)+sk0.y };
        float2 y1 = { fmaxf(sf[nt][2]+b1v,0.f)+sk1.x, fmaxf(sf[nt][3]+b1v,0.f)+sk1.y };
        *(float2*)(Y + ybase + (size_t)row0*NTOK + col) = y0;
        *(float2*)(Y + ybase + (size_t)row1*NTOK + col) = y1;
        s0 += y0.x + y0.y;  q0 += y0.x*y0.x + y0.y*y0.y;
        s1 += y1.x + y1.y;  q1 += y1.x*y1.x + y1.y*y1.y;
    }
    s0 += __shfl_xor_sync(0xffffffffu, s0, 1); s0 += __shfl_xor_sync(0xffffffffu, s0, 2);
    q0 += __shfl_xor_sync(0xffffffffu, q0, 1); q0 += __shfl_xor_sync(0xffffffffu, q0, 2);
    s1 += __shfl_xor_sync(0xffffffffu, s1, 1); s1 += __shfl_xor_sync(0xffffffffu, s1, 2);
    q1 += __shfl_xor_sync(0xffffffffu, q1, 1); q1 += __shfl_xor_sync(0xffffffffu, q1, 2);
    if (j == 0) {
        int part = b*32 + blockIdx.x;
        g_ps[row0*64 + part] = s0;  g_pq[row0*64 + part] = q0;
        g_ps[row1*64 + part] = s1;  g_pq[row1*64 + part] = q1;
    }
}

// ---------------- attention: flat grid 640, 64-token sub-tiles, 3 CTA/SM -
__global__ __launch_bounds__(256, 3) void attn_kernel(
    const uint32_t* __restrict__ Kb, const uint32_t* __restrict__ Qb,
    const uint32_t* __restrict__ Vb, uint32_t* __restrict__ Vo)
{
    extern __shared__ __align__(16) uint32_t smu[];
    uint32_t* Ksu = smu;                 // [128 r][36]
    uint32_t* Qsu = Ksu + 128*36;        // [2][64 c][36]
    uint32_t* Vsu = Qsu + 2*64*36;       // [2][64 d][36]

    const int ux = blockIdx.x;
    const int unit = ux >> 4, bh = ux & 15;
    const int b = bh >> 3, h = bh & 7;
    const int it = U_IT[unit], ch = U_CH[unit];
    const int i0 = it*TB;
    const int jlo = ch*4;
    const int jhi = (jlo+3 < it) ? jlo+3 : it;
    const int st_lo = 2*jlo, st_hi = 2*jhi + 1;   // 64-token sub-tiles

    const int tid = threadIdx.x, w = tid>>5, lane = tid&31;
    const int g = lane>>2, j = lane&3, wrow = w*16;
    const uint32_t oA36 = laneA(lane, 36);
    const uint32_t oB36 = laneB(lane, 36);

    const size_t rowKQ = (size_t)b*NTOK*256 + h*32;
    const size_t rowV  = ((size_t)b*FF + h*64)*1024;

    #pragma unroll
    for (int i=0;i<4;i++){
        int idx = tid + i*256, r = idx>>3, seg = idx&7;
        cp16(smem_u32(Ksu + r*36 + seg*4), Kb + rowKQ + (size_t)(i0+r)*256 + seg*4);
    }
    {
        int j0 = st_lo*64;
        #pragma unroll
        for (int i=0;i<2;i++){
            int idx = tid + i*256, r = idx>>3, seg = idx&7;
            cp16(smem_u32(Qsu + r*36 + seg*4), Qb + rowKQ + (size_t)(j0+r)*256 + seg*4);
            cp16(smem_u32(Vsu + r*36 + seg*4), Vb + rowV + (size_t)r*1024 + (j0>>1) + seg*4);
        }
    }
    CP_COMMIT;

    float l0 = 0.f, l1 = 0.f;
    float ot[8][4];
    #pragma unroll
    for (int nt=0;nt<8;nt++){ ot[nt][0]=ot[nt][1]=ot[nt][2]=ot[nt][3]=0.f; }

    const uint32_t kbase = smem_u32(Ksu) + wrow*36*4 + oA36;

    for (int st = st_lo; st <= st_hi; st++) {
        const int cur = (st - st_lo) & 1;
        const uint32_t qbase = smem_u32(Qsu + cur*64*36) + oB36;
        const uint32_t vbase = smem_u32(Vsu + cur*64*36) + oB36;
        CP_WAIT0;
        __syncthreads();
        if (st < st_hi) {
            uint32_t* Qn = Qsu + (cur^1)*64*36;
            uint32_t* Vn = Vsu + (cur^1)*64*36;
            int j0n = (st+1)*64;
            #pragma unroll
            for (int i=0;i<2;i++){
                int idx = tid + i*256, r = idx>>3, seg = idx&7;
                cp16(smem_u32(Qn + r*36 + seg*4), Qb + rowKQ + (size_t)(j0n+r)*256 + seg*4);
                cp16(smem_u32(Vn + r*36 + seg*4), Vb + rowV + (size_t)r*1024 + (j0n>>1) + seg*4);
            }
            CP_COMMIT;
        }

        // ---- S = K.Q over 64 cols ----
        float sf[8][4];
        #pragma unroll
        for (int nt=0;nt<8;nt++){ sf[nt][0]=sf[nt][1]=sf[nt][2]=sf[nt][3]=0.f; }
        #pragma unroll
        for (int kg = 0; kg < 4; kg++) {
            uint32_t aa[4], bb[4];
            ldsm4(aa, kbase + kg*8*4);
            #pragma unroll
            for (int ntp = 0; ntp < 4; ntp++) {
                ldsm4(bb, qbase + (ntp*16*36 + kg*8)*4);
                mma4(sf[2*ntp],   aa, bb[0], bb[1]);
                mma4(sf[2*ntp+1], aa, bb[2], bb[3]);
            }
        }
        // ---- P = 2^S ; accumulate l ----
        #pragma unroll
        for (int nt=0; nt<8; nt++) {
            sf[nt][0] = ex2f(sf[nt][0]);
            sf[nt][1] = ex2f(sf[nt][1]);
            sf[nt][2] = ex2f(sf[nt][2]);
            sf[nt][3] = ex2f(sf[nt][3]);
            l0 += sf[nt][0] + sf[nt][1];
            l1 += sf[nt][2] + sf[nt][3];
        }
        // ---- O += P.V ; P A-fragment = S C-fragment ----
        #pragma unroll
        for (int kg = 0; kg < 4; kg++) {
            uint32_t aa[4], bb[4];
            aa[0] = pack_bf16(sf[2*kg  ][0], sf[2*kg  ][1]);
            aa[1] = pack_bf16(sf[2*kg  ][2], sf[2*kg  ][3]);
            aa[2] = pack_bf16(sf[2*kg+1][0], sf[2*kg+1][1]);
            aa[3] = pack_bf16(sf[2*kg+1][2], sf[2*kg+1][3]);
            #pragma unroll
            for (int ntp = 0; ntp < 4; ntp++) {
                ldsm4(bb, vbase + (ntp*16*36 + kg*8)*4);
                mma4(ot[2*ntp],   aa, bb[0], bb[1]);
                mma4(ot[2*ntp+1], aa, bb[2], bb[3]);
            }
        }
    }

    l0 += __shfl_xor_sync(0xffffffffu, l0, 1);
    l0 += __shfl_xor_sync(0xffffffffu, l0, 2);
    l1 += __shfl_xor_sync(0xffffffffu, l1, 1);
    l1 += __shfl_xor_sync(0xffffffffu, l1, 2);

    if (it < 4) {
        float inv0 = 1.0f/l0, inv1 = 1.0f/l1;
        size_t d0 = ((size_t)b*NTOK + i0 + wrow + g)*256 + h*32;
        size_t d1 = ((size_t)b*NTOK + i0 + wrow + g + 8)*256 + h*32;
        #pragma unroll
        for (int nt=0; nt<8; nt++) {
            Vo[d0 + nt*4 + j] = pack_bf16(ot[nt][0]*inv0, ot[nt][1]*inv0);
            Vo[d1 + nt*4 + j] = pack_bf16(ot[nt][2]*inv1, ot[nt][3]*inv1);
        }
    } else {
        const int p = ((b*NH + h)*12 + (it-4))*4 + ch;
        uint32_t* op = g_Opb + (size_t)p*TB*32;
        #pragma unroll
        for (int nt=0; nt<8; nt++) {
            op[(wrow+g  )*32 + nt*4 + j] = pack_bf16(ot[nt][0], ot[nt][1]);
            op[(wrow+g+8)*32 + nt*4 + j] = pack_bf16(ot[nt][2], ot[nt][3]);
        }
        if (j == 0) {
            g_lp[p*TB + wrow+g  ] = l0;
            g_lp[p*TB + wrow+g+8] = l1;
        }
    }
}

// ---------------- attention merge: grid 768 ------------------------------
__global__ __launch_bounds__(256) void attn_merge_kernel(uint32_t* __restrict__ Vo)
{
    const int m = blockIdx.x;
    const int grp = m & 3, mm = m >> 2;
    const int itx = mm >> 4, bh = mm & 15;
    const int b = bh >> 3, h = bh & 7;
    const int it = 4 + itx;
    const int nch = it/4 + 1;               // 2..4
    const int pbase = ((b*NH + h)*12 + itx)*4;
    const int t = threadIdx.x;
    const int r  = grp*32 + (t >> 3);
    const int wq = (t & 7) * 4;

    const uint32_t* base = g_Opb + (size_t)pbase*TB*32 + r*32 + wq;
    uint4 v0 = *(const uint4*)(base);
    uint4 v1 = *(const uint4*)(base + TB*32);
    float l = g_lp[pbase*TB + r] + g_lp[(pbase+1)*TB + r];

    float acc[8];
    acc[0] = __uint_as_float(v0.x << 16)         + __uint_as_float(v1.x << 16);
    acc[1] = __uint_as_float(v0.x & 0xffff0000u) + __uint_as_float(v1.x & 0xffff0000u);
    acc[2] = __uint_as_float(v0.y << 16)         + __uint_as_float(v1.y << 16);
    acc[3] = __uint_as_float(v0.y & 0xffff0000u) + __uint_as_float(v1.y & 0xffff0000u);
    acc[4] = __uint_as_float(v0.z << 16)         + __uint_as_float(v1.z << 16);
    acc[5] = __uint_as_float(v0.z & 0xffff0000u) + __uint_as_float(v1.z & 0xffff0000u);
    acc[6] = __uint_as_float(v0.w << 16)         + __uint_as_float(v1.w << 16);
    acc[7] = __uint_as_float(v0.w & 0xffff0000u) + __uint_as_float(v1.w & 0xffff0000u);

    #pragma unroll 2
    for (int c = 2; c < nch; c++) {
        uint4 v = *(const uint4*)(base + (size_t)c*TB*32);
        l += g_lp[(pbase+c)*TB + r];
        acc[0] += __uint_as_float(v.x << 16);
        acc[1] += __uint_as_float(v.x & 0xffff0000u);
        acc[2] += __uint_as_float(v.y << 16);
        acc[3] += __uint_as_float(v.y & 0xffff0000u);
        acc[4] += __uint_as_float(v.z << 16);
        acc[5] += __uint_as_float(v.z & 0xffff0000u);
        acc[6] += __uint_as_float(v.w << 16);
        acc[7] += __uint_as_float(v.w & 0xffff0000u);
    }
    float inv = 1.0f/l;
    uint4 o;
    o.x = pack_bf16(acc[0]*inv, acc[1]*inv);
    o.y = pack_bf16(acc[2]*inv, acc[3]*inv);
    o.z = pack_bf16(acc[4]*inv, acc[5]*inv);
    o.w = pack_bf16(acc[6]*inv, acc[7]*inv);
    *(uint4*)(Vo + ((size_t)b*NTOK + it*TB + r)*256 + h*32 + wq) = o;
}

// ---------------- BN finalize + apply ----------------
__global__ void bn_finalize_kernel() {
    const int c = blockIdx.x, t = threadIdx.x;
    float s = g_ps[c*64 + t] + g_ps[c*64 + 32 + t];
    float q = g_pq[c*64 + t] + g_pq[c*64 + 32 + t];
    #pragma unroll
    for (int o = 16; o; o >>= 1) {
        s += __shfl_xor_sync(0xffffffffu, s, o);
        q += __shfl_xor_sync(0xffffffffu, q, o);
    }
    if (t == 0) {
        float mean = s / (float)(Bb*NTOK);
        float var  = q / (float)(Bb*NTOK) - mean*mean;
        g_mean[c] = mean;
        g_istd[c] = rsqrtf(var + BN_EPS);
    }
}

__global__ __launch_bounds__(256) void bn_apply_kernel(
    const float* __restrict__ gamma, const float* __restrict__ beta,
    float* __restrict__ out)
{
    int idx = blockIdx.x*256 + threadIdx.x;   // 65536 threads, 4 float4 each
    #pragma unroll
    for (int k = 0; k < 4; k++) {
        int i = idx + k*65536;
        int c = (i >> 9) & (COUT-1);
        float4 v = *((const float4*)g_y + i);
        float mu = g_mean[c], is = g_istd[c]*gamma[c], be = beta[c];
        float4 o;
        o.x = (v.x-mu)*is + be; o.y = (v.y-mu)*is + be;
        o.z = (v.z-mu)*is + be; o.w = (v.w-mu)*is + be;
        *((float4*)out + i) = o;
    }
}

// ---------------- launch ----------------
extern "C" void kernel_launch(void* const* d_in, const int* in_sizes, int n_in,
                              void* d_out, int out_size)
{
    const float* x     = (const float*)d_in[0];
    const float* WK    = (const float*)d_in[1];
    const float* WQ    = (const float*)d_in[2];
    const float* WV    = (const float*)d_in[3];
    const float* Wo    = (const float*)d_in[4];
    const float* bo    = (const float*)d_in[5];
    const float* gamma = (const float*)d_in[6];
    const float* beta  = (const float*)d_in[7];
    float* out = (float*)d_out;

    uint32_t *pK, *pQ, *pV, *pVo;
    float *pY;
    cudaGetSymbolAddress((void**)&pK,  g_Kb);
    cudaGetSymbolAddress((void**)&pQ,  g_Qb);
    cudaGetSymbolAddress((void**)&pV,  g_Vb);
    cudaGetSymbolAddress((void**)&pVo, g_Vo);
    cudaGetSymbolAddress((void**)&pY,  g_y);

    prep_kernel<<<768, 256>>>(WK, WQ, WV, Wo, x);

    dim3 gq(NTOK/64, 12, Bb);
    qkv_kernel<<<gq, 256>>>(pK, pQ, pV);

    size_t smem = (size_t)(128*36 + 2*64*36 + 2*64*36) * 4;
    cudaFuncSetAttribute(attn_kernel, cudaFuncAttributeMaxDynamicSharedMemorySize, (int)smem);
    attn_kernel<<<640, 256, smem>>>(pK, pQ, pV, pVo);

    attn_merge_kernel<<<768, 256>>>(pVo);

    dim3 gp(NTOK/64, COUT/128, Bb);
    proj_kernel<<<gp, 256>>>(pVo, bo, x, pY);

    bn_finalize_kernel<<<COUT, 32>>>();
    bn_apply_kernel<<<256, 256>>>(gamma, beta, out);
}

// round 13
// speedup vs baseline: 1.1000x; 1.1000x over previous
#include <cuda_runtime.h>
#include <cuda_bf16.h>
#include <math.h>
#include <stdint.h>

#define Bb    2
#define CIN   256
#define FF    512
#define COUT  256
#define NH    8
#define DH    64
#define NTOK  2048
#define TB    128
#define Tt    16
#define KSCALE (0.08654104f)   // log2(e)/16
#define BN_EPS 1e-5f

// ---------------- scratch (bf16 packed in uint32 words) ----------------
__device__ uint32_t g_Wb[4*65536];        // WK,WQ,WV rows 128w; Wo rows 256w
__device__ uint32_t g_Xt[Bb*NTOK*(CIN/2)];// [b][n][c/2]
__device__ uint32_t g_Kb[Bb*NTOK*FF/2];   // [b][n][f/2]  (pre-scaled log2e/16)
__device__ uint32_t g_Qb[Bb*NTOK*FF/2];   // [b][n][f/2]
__device__ uint32_t g_Vb[Bb*FF*NTOK/2];   // [b][f][n/2]
__device__ uint32_t g_Vo[Bb*NTOK*FF/2];   // [b][n][f/2]
__device__ float g_y [Bb*COUT*NTOK];      // [b][c][n]
__device__ uint32_t g_Opb[Bb*NH*12*4*TB*(DH/2)];  // partials (it>=4), bf16
__device__ float g_lp[Bb*NH*12*4*TB];
__device__ float g_ps[COUT*64];
__device__ float g_pq[COUT*64];
__device__ float g_mean[COUT];
__device__ float g_istd[COUT];

// 40 units per bh, chunk = 4 j-tiles, LPT order (proven in R9)
__constant__ int8_t U_IT[40] = {3,4,5,6,7,7,8,8,9,9,10,10,11,11,11,12,12,12,
                                13,13,13,14,14,14,15,15,15,15,
                                2,6,10,14, 1,5,9,13, 0,4,8,12};
__constant__ int8_t U_CH[40] = {0,0,0,0,0,1,0,1,0,1,0,1,0,1,2,0,1,2,
                                0,1,2,0,1,2,0,1,2,3,
                                0,1,2,3, 0,1,2,3, 0,1,2,3};

// ---------------- helpers ----------------
__device__ __forceinline__ uint32_t pack_bf16(float lo, float hi) {
    uint32_t r;
    asm("cvt.rn.bf16x2.f32 %0, %1, %2;" : "=r"(r) : "f"(hi), "f"(lo));
    return r;
}
__device__ __forceinline__ float ex2f(float x) {
    float y;
    asm("ex2.approx.f32 %0, %1;" : "=f"(y) : "f"(x));
    return y;
}
__device__ __forceinline__ void mma4(float d[4], const uint32_t a[4],
                                     uint32_t b0, uint32_t b1)
{
    asm volatile(
      "mma.sync.aligned.m16n8k16.row.col.f32.bf16.bf16.f32 "
      "{%0,%1,%2,%3}, {%4,%5,%6,%7}, {%8,%9}, {%0,%1,%2,%3};"
      : "+f"(d[0]), "+f"(d[1]), "+f"(d[2]), "+f"(d[3])
      : "r"(a[0]), "r"(a[1]), "r"(a[2]), "r"(a[3]), "r"(b0), "r"(b1));
}
__device__ __forceinline__ void ldsm4(uint32_t r[4], uint32_t addr) {
    asm volatile("ldmatrix.sync.aligned.m8n8.x4.shared.b16 {%0,%1,%2,%3}, [%4];"
        : "=r"(r[0]), "=r"(r[1]), "=r"(r[2]), "=r"(r[3]) : "r"(addr));
}
__device__ __forceinline__ uint32_t smem_u32(const void* p) {
    return (uint32_t)__cvta_generic_to_shared(p);
}
__device__ __forceinline__ void cp16(uint32_t s, const void* g) {
    asm volatile("cp.async.cg.shared.global [%0], [%1], 16;" :: "r"(s), "l"(g));
}
#define CP_COMMIT asm volatile("cp.async.commit_group;")
#define CP_WAIT0  asm volatile("cp.async.wait_group 0;")
#define CP_WAIT1  asm volatile("cp.async.wait_group 1;")

__device__ __forceinline__ uint32_t laneA(int l, int S) {
    return (uint32_t)((((l&7) + ((l>>3)&1)*8)*S + (l>>4)*4) * 4);
}
__device__ __forceinline__ uint32_t laneB(int l, int S) {
    return (uint32_t)((((l&7) + ((l>>4)&1)*8)*S + ((l>>3)&1)*4) * 4);
}

// ---------------- prep: weights -> bf16; X -> bf16 transposed ------------
__global__ __launch_bounds__(256) void prep_kernel(
    const float* __restrict__ WK, const float* __restrict__ WQ,
    const float* __restrict__ WV, const float* __restrict__ Wo,
    const float* __restrict__ X)
{
    const int tid = threadIdx.x;
    if (blockIdx.x < 256) {
        int e8 = blockIdx.x*256 + tid;
        int e  = e8*8;
        const float* src; int off;
        if      (e < 131072) { src = WK; off = e; }
        else if (e < 262144) { src = WQ; off = e - 131072; }
        else if (e < 393216) { src = WV; off = e - 262144; }
        else                 { src = Wo; off = e - 393216; }
        float4 a = *(const float4*)(src + off);
        float4 c = *(const float4*)(src + off + 4);
        uint4 o;
        o.x = pack_bf16(a.x, a.y); o.y = pack_bf16(a.z, a.w);
        o.z = pack_bf16(c.x, c.y); o.w = pack_bf16(c.z, c.w);
        *(uint4*)(g_Wb + e8*4) = o;
    } else {
        __shared__ float ts[32][68];
        int bx = blockIdx.x - 256;
        int b  = bx >> 8;
        int t8 = bx & 255;
        int n0 = (t8 >> 3) * 64;
        int c0 = (t8 & 7) * 32;
        const float* Xb = X + (size_t)b*CIN*NTOK;
        #pragma unroll
        for (int i = 0; i < 2; i++) {
            int c = (tid>>4) + i*16, n4 = (tid&15)*4;
            float4 v = *(const float4*)(Xb + (size_t)(c0+c)*NTOK + n0 + n4);
            *(float4*)&ts[c][n4] = v;
        }
        __syncthreads();
        int n = tid>>2, w0 = tid&3;
        size_t dst = ((size_t)b*NTOK + n0 + n)*128 + (c0>>1);
        #pragma unroll
        for (int ii = 0; ii < 4; ii++) {
            int w = w0 + 4*ii;
            g_Xt[dst + w] = pack_bf16(ts[2*w][n], ts[2*w+1][n]);
        }
    }
}

// ---------------- fused QKV GEMM: 3-stage pipeline, grid (32,12,2) -------
__global__ __launch_bounds__(256) void qkv_kernel(
    uint32_t* __restrict__ Kb, uint32_t* __restrict__ Qb,
    uint32_t* __restrict__ Vb)
{
    __shared__ __align__(16) uint32_t Wsu[3][128*20];
    __shared__ __align__(16) uint32_t Xsu[3][64*20];
    const int b = blockIdx.z, mb = blockIdx.y, n0 = blockIdx.x*64;
    const int sel = mb >> 2, m0 = (mb & 3)*128;
    const uint32_t* W  = g_Wb + sel*65536;
    const uint32_t* Xp = g_Xt + ((size_t)b*NTOK + n0)*128;
    const int tid = threadIdx.x, w = tid>>5, lane = tid&31;
    const int g = lane>>2, j = lane&3, wrow = w*16;
    const uint32_t oA = laneA(lane, 20), oB = laneB(lane, 20);

    float sf[8][4];
    #pragma unroll
    for (int nt=0;nt<8;nt++){ sf[nt][0]=sf[nt][1]=sf[nt][2]=sf[nt][3]=0.f; }

    // prologue: chunks 0 and 1 in flight
    #pragma unroll
    for (int p = 0; p < 2; p++) {
        #pragma unroll
        for (int i=0;i<2;i++){
            int idx = tid + i*256, m = idx>>2, seg = idx&3;
            cp16(smem_u32(&Wsu[p][m*20 + seg*4]), W + (size_t)(m0+m)*128 + p*16 + seg*4);
        }
        {   int r = tid>>2, seg = tid&3;
            cp16(smem_u32(&Xsu[p][r*20 + seg*4]), Xp + (size_t)r*128 + p*16 + seg*4);
        }
        CP_COMMIT;
    }

    for (int c = 0; c < 8; c++) {
        if (c == 7) { CP_WAIT0; } else { CP_WAIT1; }
        __syncthreads();
        if (c < 6) {
            int nb = (c+2) % 3;
            #pragma unroll
            for (int i=0;i<2;i++){
                int idx = tid + i*256, m = idx>>2, seg = idx&3;
                cp16(smem_u32(&Wsu[nb][m*20 + seg*4]),
                     W + (size_t)(m0+m)*128 + (c+2)*16 + seg*4);
            }
            {   int r = tid>>2, seg = tid&3;
                cp16(smem_u32(&Xsu[nb][r*20 + seg*4]),
                     Xp + (size_t)r*128 + (c+2)*16 + seg*4);
            }
            CP_COMMIT;
        }
        int cur = c % 3;
        const uint32_t wbase = smem_u32(Wsu[cur]) + wrow*20*4 + oA;
        const uint32_t xbase = smem_u32(Xsu[cur]) + oB;
        uint32_t a0[4], a1[4], bb[4];
        ldsm4(a0, wbase);
        ldsm4(a1, wbase + 8*4);
        #pragma unroll
        for (int ntp = 0; ntp < 4; ntp++) {
            ldsm4(bb, xbase + (ntp*16*20)*4);
            mma4(sf[2*ntp],   a0, bb[0], bb[1]);
            mma4(sf[2*ntp+1], a0, bb[2], bb[3]);
            ldsm4(bb, xbase + (ntp*16*20 + 8)*4);
            mma4(sf[2*ntp],   a1, bb[0], bb[1]);
            mma4(sf[2*ntp+1], a1, bb[2], bb[3]);
        }
    }
    __syncthreads();

    if (sel == 2) {
        size_t basew = ((size_t)b*FF + m0)*1024 + (n0>>1);
        #pragma unroll
        for (int nt=0; nt<8; nt++) {
            Vb[basew + (size_t)(wrow+g  )*1024 + nt*4 + j] = pack_bf16(sf[nt][0], sf[nt][1]);
            Vb[basew + (size_t)(wrow+g+8)*1024 + nt*4 + j] = pack_bf16(sf[nt][2], sf[nt][3]);
        }
    } else {
        const float scale = (sel==0) ? KSCALE : 1.f;
        __nv_bfloat16* tileh = (__nv_bfloat16*)&Wsu[0][0];
        #pragma unroll
        for (int nt=0; nt<8; nt++) {
            int c = nt*8 + 2*j;
            tileh[(c  )*136 + wrow+g  ] = __float2bfloat16(sf[nt][0]*scale);
            tileh[(c+1)*136 + wrow+g  ] = __float2bfloat16(sf[nt][1]*scale);
            tileh[(c  )*136 + wrow+g+8] = __float2bfloat16(sf[nt][2]*scale);
            tileh[(c+1)*136 + wrow+g+8] = __float2bfloat16(sf[nt][3]*scale);
        }
        __syncthreads();
        uint32_t* C = (sel==0) ? Kb : Qb;
        const uint32_t* tw = (const uint32_t*)tileh;
        int cc = tid>>2, seg = tid&3;
        size_t dstw = ((size_t)b*NTOK + n0 + cc)*256 + (m0>>1) + seg*16;
        #pragma unroll
        for (int q=0; q<4; q++) {
            uint4 v = *(const uint4*)(tw + cc*68 + seg*16 + q*4);
            *(uint4*)(C + dstw + q*4) = v;
        }
    }
}

// ---------------- proj: 3-stage pipeline, grid (32,2,2) ------------------
__global__ __launch_bounds__(256) void proj_kernel(
    const uint32_t* __restrict__ Vo,
    const float* __restrict__ bias, const float* __restrict__ skip,
    float* __restrict__ Y)
{
    __shared__ __align__(16) uint32_t Wsu[3][128*20];
    __shared__ __align__(16) uint32_t Xsu[3][64*20];
    const int b = blockIdx.z, m0 = blockIdx.y*128, n0 = blockIdx.x*64;
    const int tid = threadIdx.x, w = tid>>5, lane = tid&31;
    const int g = lane>>2, j = lane&3, wrow = w*16;
    const uint32_t* W  = g_Wb + 3*65536;
    const uint32_t* Vp = Vo + ((size_t)b*NTOK + n0)*256;
    const uint32_t oA = laneA(lane, 20), oB = laneB(lane, 20);

    float sf[8][4];
    #pragma unroll
    for (int nt=0;nt<8;nt++){ sf[nt][0]=sf[nt][1]=sf[nt][2]=sf[nt][3]=0.f; }

    #pragma unroll
    for (int p = 0; p < 2; p++) {
        #pragma unroll
        for (int i=0;i<2;i++){
            int idx = tid + i*256, m = idx>>2, seg = idx&3;
            cp16(smem_u32(&Wsu[p][m*20 + seg*4]), W + (size_t)(m0+m)*256 + p*16 + seg*4);
        }
        {   int r = tid>>2, seg = tid&3;
            cp16(smem_u32(&Xsu[p][r*20 + seg*4]), Vp + (size_t)r*256 + p*16 + seg*4);
        }
        CP_COMMIT;
    }

    for (int c = 0; c < 16; c++) {
        if (c == 15) { CP_WAIT0; } else { CP_WAIT1; }
        __syncthreads();
        if (c < 14) {
            int nb = (c+2) % 3;
            #pragma unroll
            for (int i=0;i<2;i++){
                int idx = tid + i*256, m = idx>>2, seg = idx&3;
                cp16(smem_u32(&Wsu[nb][m*20 + seg*4]),
                     W + (size_t)(m0+m)*256 + (c+2)*16 + seg*4);
            }
            {   int r = tid>>2, seg = tid&3;
                cp16(smem_u32(&Xsu[nb][r*20 + seg*4]),
                     Vp + (size_t)r*256 + (c+2)*16 + seg*4);
            }
            CP_COMMIT;
        }
        int cur = c % 3;
        const uint32_t wbase = smem_u32(Wsu[cur]) + wrow*20*4 + oA;
        const uint32_t xbase = smem_u32(Xsu[cur]) + oB;
        uint32_t a0[4], a1[4], bb[4];
        ldsm4(a0, wbase);
        ldsm4(a1, wbase + 8*4);
        #pragma unroll
        for (int ntp = 0; ntp < 4; ntp++) {
            ldsm4(bb, xbase + (ntp*16*20)*4);
            mma4(sf[2*ntp],   a0, bb[0], bb[1]);
            mma4(sf[2*ntp+1], a0, bb[2], bb[3]);
            ldsm4(bb, xbase + (ntp*16*20 + 8)*4);
            mma4(sf[2*ntp],   a1, bb[0], bb[1]);
            mma4(sf[2*ntp+1], a1, bb[2], bb[3]);
        }
    }

    const int row0 = m0 + wrow + g, row1 = row0 + 8;
    const float b0v = bias[row0], b1v = bias[row1];
    const size_t ybase = (size_t)b*COUT*NTOK;
    float s0=0.f,q0=0.f,s1=0.f,q1=0.f;
    #pragma unroll
    for (int nt=0; nt<8; nt++) {
        int col = n0 + nt*8 + 2*j;
        float2 sk0 = *(const float2*)(skip + ybase + (size_t)row0*NTOK + col);
        float2 sk1 = *(const float2*)(skip + ybase + (size_t)row1*NTOK + col);
        float2 y0 = { fmaxf(sf[nt][0]+b0v,0.f)+sk0.x, fmaxf(sf[nt][1]+b0v,0.f)+sk0.y };
        float2 y1 = { fmaxf(sf[nt][2]+b1v,0.f)+sk1.x, fmaxf(sf[nt][3]+b1v,0.f)+sk1.y };
        *(float2*)(Y + ybase + (size_t)row0*NTOK + col) = y0;
        *(float2*)(Y + ybase + (size_t)row1*NTOK + col) = y1;
        s0 += y0.x + y0.y;  q0 += y0.x*y0.x + y0.y*y0.y;
        s1 += y1.x + y1.y;  q1 += y1.x*y1.x + y1.y*y1.y;
    }
    s0 += __shfl_xor_sync(0xffffffffu, s0, 1); s0 += __shfl_xor_sync(0xffffffffu, s0, 2);
    q0 += __shfl_xor_sync(0xffffffffu, q0, 1); q0 += __shfl_xor_sync(0xffffffffu, q0, 2);
    s1 += __shfl_xor_sync(0xffffffffu, s1, 1); s1 += __shfl_xor_sync(0xffffffffu, s1, 2);
    q1 += __shfl_xor_sync(0xffffffffu, q1, 1); q1 += __shfl_xor_sync(0xffffffffu, q1, 2);
    if (j == 0) {
        int part = b*32 + blockIdx.x;
        g_ps[row0*64 + part] = s0;  g_pq[row0*64 + part] = q0;
        g_ps[row1*64 + part] = s1;  g_pq[row1*64 + part] = q1;
    }
}

// ---------------- attention: flat grid 640, P in registers (exact R9) ----
__global__ __launch_bounds__(256, 2) void attn_kernel(
    const uint32_t* __restrict__ Kb, const uint32_t* __restrict__ Qb,
    const uint32_t* __restrict__ Vb, uint32_t* __restrict__ Vo)
{
    extern __shared__ __align__(16) uint32_t smu[];
    uint32_t* Ksu = smu;                 // [128 r][36]
    uint32_t* Qsu = Ksu + 128*36;        // [2][128 c][36]
    uint32_t* Vsu = Qsu + 2*128*36;      // [2][64 d][68]

    const int ux = blockIdx.x;
    const int unit = ux >> 4, bh = ux & 15;
    const int b = bh >> 3, h = bh & 7;
    const int it = U_IT[unit], ch = U_CH[unit];
    const int i0 = it*TB;
    const int jlo = ch*4;
    const int jhi = (jlo+3 < it) ? jlo+3 : it;

    const int tid = threadIdx.x, w = tid>>5, lane = tid&31;
    const int g = lane>>2, j = lane&3, wrow = w*16;
    const uint32_t oA36 = laneA(lane, 36);
    const uint32_t oB36 = laneB(lane, 36);
    const uint32_t oB68 = laneB(lane, 68);

    const size_t rowKQ = (size_t)b*NTOK*256 + h*32;
    const size_t rowV  = ((size_t)b*FF + h*64)*1024;

    #pragma unroll
    for (int i=0;i<4;i++){
        int idx = tid + i*256, r = idx>>3, seg = idx&7;
        cp16(smem_u32(Ksu + r*36 + seg*4), Kb + rowKQ + (size_t)(i0+r)*256 + seg*4);
    }
    {
        int j0 = jlo*TB;
        #pragma unroll
        for (int i=0;i<4;i++){
            int idx = tid + i*256, r = idx>>3, seg = idx&7;
            cp16(smem_u32(Qsu + r*36 + seg*4), Qb + rowKQ + (size_t)(j0+r)*256 + seg*4);
        }
        #pragma unroll
        for (int i=0;i<4;i++){
            int idx = tid + i*256, d = idx>>4, seg = idx&15;
            cp16(smem_u32(Vsu + d*68 + seg*4), Vb + rowV + (size_t)d*1024 + (j0>>1) + seg*4);
        }
    }
    CP_COMMIT;

    float l0 = 0.f, l1 = 0.f;
    float ot[8][4];
    #pragma unroll
    for (int nt=0;nt<8;nt++){ ot[nt][0]=ot[nt][1]=ot[nt][2]=ot[nt][3]=0.f; }

    for (int jt = jlo; jt <= jhi; jt++) {
        const int cur = (jt - jlo) & 1;
        const uint32_t* Qc = Qsu + cur*128*36;
        const uint32_t* Vc = Vsu + cur*64*68;
        CP_WAIT0;
        __syncthreads();
        if (jt < jhi) {
            uint32_t* Qn = Qsu + (cur^1)*128*36;
            uint32_t* Vn = Vsu + (cur^1)*64*68;
            int j0n = (jt+1)*TB;
            #pragma unroll
            for (int i=0;i<4;i++){
                int idx = tid + i*256, r = idx>>3, seg = idx&7;
                cp16(smem_u32(Qn + r*36 + seg*4), Qb + rowKQ + (size_t)(j0n+r)*256 + seg*4);
            }
            #pragma unroll
            for (int i=0;i<4;i++){
                int idx = tid + i*256, d = idx>>4, seg = idx&15;
                cp16(smem_u32(Vn + d*68 + seg*4), Vb + rowV + (size_t)d*1024 + (j0n>>1) + seg*4);
            }
            CP_COMMIT;
        }

        const uint32_t kbase = smem_u32(Ksu) + wrow*36*4 + oA36;

        #pragma unroll
        for (int h2 = 0; h2 < 2; h2++) {
            const int chh = h2*64;
            const uint32_t qbase = smem_u32(Qc) + chh*36*4 + oB36;
            const uint32_t vbase = smem_u32(Vc) + h2*32*4 + oB68;

            float sf[8][4];
            #pragma unroll
            for (int nt=0;nt<8;nt++){ sf[nt][0]=sf[nt][1]=sf[nt][2]=sf[nt][3]=0.f; }
            #pragma unroll
            for (int kg = 0; kg < 4; kg++) {
                uint32_t aa[4], bb[4];
                ldsm4(aa, kbase + kg*8*4);
                #pragma unroll
                for (int ntp = 0; ntp < 4; ntp++) {
                    ldsm4(bb, qbase + (ntp*16*36 + kg*8)*4);
                    mma4(sf[2*ntp],   aa, bb[0], bb[1]);
                    mma4(sf[2*ntp+1], aa, bb[2], bb[3]);
                }
            }
            #pragma unroll
            for (int nt=0; nt<8; nt++) {
                sf[nt][0] = ex2f(sf[nt][0]);
                sf[nt][1] = ex2f(sf[nt][1]);
                sf[nt][2] = ex2f(sf[nt][2]);
                sf[nt][3] = ex2f(sf[nt][3]);
                l0 += sf[nt][0] + sf[nt][1];
                l1 += sf[nt][2] + sf[nt][3];
            }
            #pragma unroll
            for (int kg = 0; kg < 4; kg++) {
                uint32_t aa[4], bb[4];
                aa[0] = pack_bf16(sf[2*kg  ][0], sf[2*kg  ][1]);
                aa[1] = pack_bf16(sf[2*kg  ][2], sf[2*kg  ][3]);
                aa[2] = pack_bf16(sf[2*kg+1][0], sf[2*kg+1][1]);
                aa[3] = pack_bf16(sf[2*kg+1][2], sf[2*kg+1][3]);
                #pragma unroll
                for (int ntp = 0; ntp < 4; ntp++) {
                    ldsm4(bb, vbase + (ntp*16*68 + kg*8)*4);
                    mma4(ot[2*ntp],   aa, bb[0], bb[1]);
                    mma4(ot[2*ntp+1], aa, bb[2], bb[3]);
                }
            }
        }
    }

    l0 += __shfl_xor_sync(0xffffffffu, l0, 1);
    l0 += __shfl_xor_sync(0xffffffffu, l0, 2);
    l1 += __shfl_xor_sync(0xffffffffu, l1, 1);
    l1 += __shfl_xor_sync(0xffffffffu, l1, 2);

    if (it < 4) {
        float inv0 = 1.0f/l0, inv1 = 1.0f/l1;
        size_t d0 = ((size_t)b*NTOK + i0 + wrow + g)*256 + h*32;
        size_t d1 = ((size_t)b*NTOK + i0 + wrow + g + 8)*256 + h*32;
        #pragma unroll
        for (int nt=0; nt<8; nt++) {
            Vo[d0 + nt*4 + j] = pack_bf16(ot[nt][0]*inv0, ot[nt][1]*inv0);
            Vo[d1 + nt*4 + j] = pack_bf16(ot[nt][2]*inv1, ot[nt][3]*inv1);
        }
    } else {
        const int p = ((b*NH + h)*12 + (it-4))*4 + ch;
        uint32_t* op = g_Opb + (size_t)p*TB*32;
        #pragma unroll
        for (int nt=0; nt<8; nt++) {
            op[(wrow+g  )*32 + nt*4 + j] = pack_bf16(ot[nt][0], ot[nt][1]);
            op[(wrow+g+8)*32 + nt*4 + j] = pack_bf16(ot[nt][2], ot[nt][3]);
        }
        if (j == 0) {
            g_lp[p*TB + wrow+g  ] = l0;
            g_lp[p*TB + wrow+g+8] = l1;
        }
    }
}

// ---------------- attention merge: grid 768 (exact R9) -------------------
__global__ __launch_bounds__(256) void attn_merge_kernel(uint32_t* __restrict__ Vo)
{
    const int m = blockIdx.x;
    const int grp = m & 3, mm = m >> 2;
    const int itx = mm >> 4, bh = mm & 15;
    const int b = bh >> 3, h = bh & 7;
    const int it = 4 + itx;
    const int nch = it/4 + 1;
    const int pbase = ((b*NH + h)*12 + itx)*4;
    const int t = threadIdx.x;
    const int r  = grp*32 + (t >> 3);
    const int wq = (t & 7) * 4;

    float acc[8] = {0,0,0,0,0,0,0,0};
    float l = 0.f;
    #pragma unroll 4
    for (int c = 0; c < nch; c++) {
        uint4 v = *(const uint4*)(g_Opb + (size_t)(pbase+c)*TB*32 + r*32 + wq);
        l += g_lp[(pbase+c)*TB + r];
        acc[0] += __uint_as_float(v.x << 16);
        acc[1] += __uint_as_float(v.x & 0xffff0000u);
        acc[2] += __uint_as_float(v.y << 16);
        acc[3] += __uint_as_float(v.y & 0xffff0000u);
        acc[4] += __uint_as_float(v.z << 16);
        acc[5] += __uint_as_float(v.z & 0xffff0000u);
        acc[6] += __uint_as_float(v.w << 16);
        acc[7] += __uint_as_float(v.w & 0xffff0000u);
    }
    float inv = 1.0f/l;
    uint4 o;
    o.x = pack_bf16(acc[0]*inv, acc[1]*inv);
    o.y = pack_bf16(acc[2]*inv, acc[3]*inv);
    o.z = pack_bf16(acc[4]*inv, acc[5]*inv);
    o.w = pack_bf16(acc[6]*inv, acc[7]*inv);
    *(uint4*)(Vo + ((size_t)b*NTOK + it*TB + r)*256 + h*32 + wq) = o;
}

// ---------------- BN finalize + apply (exact R9) ----------------
__global__ void bn_finalize_kernel() {
    const int c = blockIdx.x, t = threadIdx.x;
    float s = g_ps[c*64 + t] + g_ps[c*64 + 32 + t];
    float q = g_pq[c*64 + t] + g_pq[c*64 + 32 + t];
    #pragma unroll
    for (int o = 16; o; o >>= 1) {
        s += __shfl_xor_sync(0xffffffffu, s, o);
        q += __shfl_xor_sync(0xffffffffu, q, o);
    }
    if (t == 0) {
        float mean = s / (float)(Bb*NTOK);
        float var  = q / (float)(Bb*NTOK) - mean*mean;
        g_mean[c] = mean;
        g_istd[c] = rsqrtf(var + BN_EPS);
    }
}

__global__ __launch_bounds__(256) void bn_apply_kernel(
    const float* __restrict__ gamma, const float* __restrict__ beta,
    float* __restrict__ out)
{
    int idx = blockIdx.x*256 + threadIdx.x;
    int i0 = idx, i1 = idx + 131072;
    int c0 = (i0 >> 9) & (COUT-1);
    int c1 = (i1 >> 9) & (COUT-1);
    float4 v0 = *((const float4*)g_y + i0);
    float4 v1 = *((const float4*)g_y + i1);
    float mu0 = g_mean[c0], is0 = g_istd[c0]*gamma[c0], be0 = beta[c0];
    float mu1 = g_mean[c1], is1 = g_istd[c1]*gamma[c1], be1 = beta[c1];
    float4 o0, o1;
    o0.x = (v0.x-mu0)*is0 + be0; o0.y = (v0.y-mu0)*is0 + be0;
    o0.z = (v0.z-mu0)*is0 + be0; o0.w = (v0.w-mu0)*is0 + be0;
    o1.x = (v1.x-mu1)*is1 + be1; o1.y = (v1.y-mu1)*is1 + be1;
    o1.z = (v1.z-mu1)*is1 + be1; o1.w = (v1.w-mu1)*is1 + be1;
    *((float4*)out + i0) = o0;
    *((float4*)out + i1) = o1;
}

// ---------------- launch ----------------
extern "C" void kernel_launch(void* const* d_in, const int* in_sizes, int n_in,
                              void* d_out, int out_size)
{
    const float* x     = (const float*)d_in[0];
    const float* WK    = (const float*)d_in[1];
    const float* WQ    = (const float*)d_in[2];
    const float* WV    = (const float*)d_in[3];
    const float* Wo    = (const float*)d_in[4];
    const float* bo    = (const float*)d_in[5];
    const float* gamma = (const float*)d_in[6];
    const float* beta  = (const float*)d_in[7];
    float* out = (float*)d_out;

    uint32_t *pK, *pQ, *pV, *pVo;
    float *pY;
    cudaGetSymbolAddress((void**)&pK,  g_Kb);
    cudaGetSymbolAddress((void**)&pQ,  g_Qb);
    cudaGetSymbolAddress((void**)&pV,  g_Vb);
    cudaGetSymbolAddress((void**)&pVo, g_Vo);
    cudaGetSymbolAddress((void**)&pY,  g_y);

    prep_kernel<<<768, 256>>>(WK, WQ, WV, Wo, x);

    dim3 gq(NTOK/64, 12, Bb);
    qkv_kernel<<<gq, 256>>>(pK, pQ, pV);

    size_t smem = (size_t)(128*36 + 2*128*36 + 2*64*68) * 4;
    cudaFuncSetAttribute(attn_kernel, cudaFuncAttributeMaxDynamicSharedMemorySize, (int)smem);
    attn_kernel<<<640, 256, smem>>>(pK, pQ, pV, pVo);

    attn_merge_kernel<<<768, 256>>>(pVo);

    dim3 gp(NTOK/64, COUT/128, Bb);
    proj_kernel<<<gp, 256>>>(pVo, bo, x, pY);

    bn_finalize_kernel<<<COUT, 32>>>();
    bn_apply_kernel<<<512, 256>>>(gamma, beta, out);
}